// round 11
// baseline (speedup 1.0000x reference)
#include <cuda_runtime.h>
#include <cuda_bf16.h>
#include <cstdint>

#define HDIM 1024
#define SDIM 2048
#define VDIM 50257
#define NBOUND 25
#define MERGED 2048
#define NBLK 148           // one block per SM
#define NTHR 1024
#define NWTOT (NBLK * 32)  // 4736 warps (unchanged)

// ---------------- device scratch ----------------
__device__ __align__(16) float g_h[2][HDIM];
__device__ __align__(16) float g_q[HDIM];
__device__ __align__(16) float g_s[SDIM];
__device__ __align__(16) float g_ctx_part[8][HDIM];
__device__ __align__(16) float g_eproj[(size_t)SDIM * HDIM];          // 8 MB
__device__ __align__(16) unsigned char g_wq[(size_t)VDIM * MERGED];   // 103 MB int8 W_out
__device__ __align__(16) float g_scale[VDIM];
__device__ __align__(16) float g_qb[VDIM];
__device__ unsigned g_M[2];
__device__ unsigned long long g_best[2];
__device__ unsigned g_bar_count, g_bar_phase;

// ---------------- helpers ----------------
__device__ __forceinline__ float warp_sum(float v) {
#pragma unroll
    for (int o = 16; o; o >>= 1) v += __shfl_xor_sync(0xffffffffu, v, o);
    return v;
}
__device__ __forceinline__ float warp_max(float v) {
#pragma unroll
    for (int o = 16; o; o >>= 1) v = fmaxf(v, __shfl_xor_sync(0xffffffffu, v, o));
    return v;
}
__device__ __forceinline__ unsigned enc_f(float f) {
    unsigned b = __float_as_uint(f);
    return (b & 0x80000000u) ? ~b : (b | 0x80000000u);
}
__device__ __forceinline__ float dec_f(unsigned u) {
    unsigned b = (u & 0x80000000u) ? (u ^ 0x80000000u) : ~u;
    return __uint_as_float(b);
}
__device__ __forceinline__ float exp2_fast(float y) {
    y = fminf(fmaxf(y, -60.f), 60.f);
    float n = rintf(y);
    float f = y - n;
    float p = 1.5403530e-4f;
    p = fmaf(p, f, 1.3333558e-3f);
    p = fmaf(p, f, 9.6181291e-3f);
    p = fmaf(p, f, 5.5504109e-2f);
    p = fmaf(p, f, 2.4022651e-1f);
    p = fmaf(p, f, 6.9314718e-1f);
    p = fmaf(p, f, 1.0f);
    return __int_as_float(((int)n + 127) << 23) * p;
}
__device__ __forceinline__ float tanh_fast(float x) {
    float e = exp2_fast(x * 2.885390081777927f);
    return 1.f - 2.f / (e + 1.f);
}
__device__ __forceinline__ float sigmoid_fast(float x) {
    float e = exp2_fast(-1.4426950408889634f * x);
    return 1.f / (1.f + e);
}

// grid-wide barrier (148 arrivals)
__device__ __forceinline__ void gsync(unsigned& tgt) {
    __syncthreads();
    if (threadIdx.x == 0) {
        __threadfence();
        unsigned v = atomicAdd(&g_bar_count, 1u);
        if (v == NBLK - 1) {
            g_bar_count = 0;
            asm volatile("st.release.gpu.u32 [%0], %1;" :: "l"(&g_bar_phase), "r"(tgt) : "memory");
        } else {
            unsigned p;
            do {
                asm volatile("ld.acquire.gpu.u32 %0, [%1];" : "=r"(p) : "l"(&g_bar_phase) : "memory");
            } while ((int)(p - tgt) < 0);
        }
    }
    __syncthreads();
    tgt++;
}

// accumulate one packed int8 quad against a float4
__device__ __forceinline__ void acc_q(float& a, unsigned u, float4 mm) {
    a = fmaf((float)(int)(signed char)(u      ), mm.x, a);
    a = fmaf((float)(int)(signed char)(u >>  8), mm.y, a);
    a = fmaf((float)(int)(signed char)(u >> 16), mm.z, a);
    a = fmaf((float)(int)(signed char)(u >> 24), mm.w, a);
}

// ---------------- the persistent mega-kernel ----------------
__global__ __launch_bounds__(NTHR, 1) void k_mega(
    const float* __restrict__ hidden, const float* __restrict__ emb,
    const float* __restrict__ emb_table,
    const float* __restrict__ W_ih, const float* __restrict__ W_hh,
    const float* __restrict__ b_ih, const float* __restrict__ b_hh,
    const float* __restrict__ We, const float* __restrict__ Wq,
    const float* __restrict__ ba, const float* __restrict__ va,
    const float* __restrict__ Wout, const float* __restrict__ bout,
    float* __restrict__ out)
{
    __shared__ __align__(16) float s_As[128 * 36];   // eproj A tile; reused as merge vec / ctx partials
    __shared__ __align__(16) float s_Bs[32 * 132];   // eproj B tile (k-major, pad 132)
    __shared__ float s_gru[8][4][6];
    __shared__ float s_red[32];
    __shared__ float s_ub[32][11];                   // per-warp row upper bounds
    __shared__ float s_nm;
    __shared__ int s_cand[32];
    __shared__ int s_cnt;
    __shared__ int s_word;

    const int tid = threadIdx.x;
    const int blk = blockIdx.x;
    const int w = tid >> 5, lane = tid & 31;
    const int gw = blk * 32 + w;

    unsigned tgt = *((volatile unsigned*)&g_bar_phase) + 1;

    // ---------- phase 0a: init + int8 quant of W_out (warp per row) ----------
    if (blk == 0 && tid < 2) { g_M[tid] = 0u; g_best[tid] = 0ull; }
    if (blk == 1) {
        for (int i = tid; i < HDIM; i += NTHR) g_h[0][i] = hidden[i];
    }
    for (int v = gw; v < VDIM; v += NWTOT) {
        const float4* src = (const float4*)(Wout + (size_t)v * MERGED);
        float am = 0.f;
#pragma unroll 4
        for (int i = 0; i < 16; i++) {
            float4 f = __ldg(src + lane + 32 * i);
            am = fmaxf(am, fmaxf(fmaxf(fabsf(f.x), fabsf(f.y)), fmaxf(fabsf(f.z), fabsf(f.w))));
        }
        am = warp_max(am);
        am = fmaxf(am, 1e-20f);
        float scale = am * (1.f / 127.f);
        float inv = 127.f / am;
        unsigned* dst = (unsigned*)(g_wq + (size_t)v * MERGED);
        float r2 = 0.f;
#pragma unroll 4
        for (int i = 0; i < 16; i++) {
            float4 f = __ldg(src + lane + 32 * i);
            int q0 = min(127, max(-127, __float2int_rn(f.x * inv)));
            int q1 = min(127, max(-127, __float2int_rn(f.y * inv)));
            int q2 = min(127, max(-127, __float2int_rn(f.z * inv)));
            int q3 = min(127, max(-127, __float2int_rn(f.w * inv)));
            float r0 = f.x - (float)q0 * scale;
            float r1 = f.y - (float)q1 * scale;
            float rr2 = f.z - (float)q2 * scale;
            float r3 = f.w - (float)q3 * scale;
            r2 = fmaf(r0, r0, r2); r2 = fmaf(r1, r1, r2);
            r2 = fmaf(rr2, rr2, r2); r2 = fmaf(r3, r3, r2);
            unsigned pk = (q0 & 0xFF) | ((q1 & 0xFF) << 8) | ((q2 & 0xFF) << 16) | ((unsigned)(q3 & 0xFF) << 24);
            __stcs(dst + lane + 32 * i, pk);
        }
        r2 = warp_sum(r2);
        if (lane == 0) {
            g_scale[v] = scale;
            g_qb[v] = sqrtf(r2);
        }
    }

    // ---------- phase 0b: eproj (blocks 0-127, one 128x128 tile each) ----------
    if (blk < 128) {
        const int ts0 = (blk >> 3) * 128;    // s-tile
        const int ta0 = (blk & 7) * 128;     // a-tile
        const int ts = tid >> 5;             // 0..31 (4 strides of 32 rows)
        const int ta = tid & 31;             // x4 cols
        float acc[4][4];
#pragma unroll
        for (int i = 0; i < 4; i++)
#pragma unroll
            for (int j = 0; j < 4; j++) acc[i][j] = 0.f;
        __syncthreads();
        for (int kt = 0; kt < 1024; kt += 32) {
            // A: [row][k] padded 36
#pragma unroll
            for (int r = 0; r < 4; r++) {
                int e0 = tid + NTHR * r;           // 0..4095
                int si = e0 >> 5, kk = e0 & 31;
                s_As[si * 36 + kk] = emb[(size_t)(ts0 + si) * 1024 + kt + kk];
            }
            // B: k-major [k][a] padded 132
#pragma unroll
            for (int r = 0; r < 4; r++) {
                int e0 = tid + NTHR * r;           // 0..4095
                int ai = e0 >> 5, kk = e0 & 31;
                s_Bs[kk * 132 + ai] = We[(size_t)(ta0 + ai) * 1024 + kt + kk];
            }
            __syncthreads();
#pragma unroll
            for (int k = 0; k < 32; k++) {
                float a0 = s_As[ts * 36 + k];
                float a1 = s_As[(ts + 32) * 36 + k];
                float a2 = s_As[(ts + 64) * 36 + k];
                float a3 = s_As[(ts + 96) * 36 + k];
                float4 b4 = *(const float4*)(s_Bs + k * 132 + ta * 4);
                acc[0][0] = fmaf(a0, b4.x, acc[0][0]); acc[0][1] = fmaf(a0, b4.y, acc[0][1]);
                acc[0][2] = fmaf(a0, b4.z, acc[0][2]); acc[0][3] = fmaf(a0, b4.w, acc[0][3]);
                acc[1][0] = fmaf(a1, b4.x, acc[1][0]); acc[1][1] = fmaf(a1, b4.y, acc[1][1]);
                acc[1][2] = fmaf(a1, b4.z, acc[1][2]); acc[1][3] = fmaf(a1, b4.w, acc[1][3]);
                acc[2][0] = fmaf(a2, b4.x, acc[2][0]); acc[2][1] = fmaf(a2, b4.y, acc[2][1]);
                acc[2][2] = fmaf(a2, b4.z, acc[2][2]); acc[2][3] = fmaf(a2, b4.w, acc[2][3]);
                acc[3][0] = fmaf(a3, b4.x, acc[3][0]); acc[3][1] = fmaf(a3, b4.y, acc[3][1]);
                acc[3][2] = fmaf(a3, b4.z, acc[3][2]); acc[3][3] = fmaf(a3, b4.w, acc[3][3]);
            }
            __syncthreads();
        }
        float4 bb = __ldg((const float4*)(ba + ta0) + ta);
#pragma unroll
        for (int i = 0; i < 4; i++) {
            float4 o = make_float4(acc[i][0] + bb.x, acc[i][1] + bb.y,
                                   acc[i][2] + bb.z, acc[i][3] + bb.w);
            *(float4*)&g_eproj[(size_t)(ts0 + ts + 32 * i) * 1024 + ta0 + ta * 4] = o;
        }
    }
    gsync(tgt);

    // ---------- decode loop ----------
    int word = 1;  // SOS
    for (int t = 0; t < NBOUND; t++) {
        const int par = t & 1;
        const int pold = par, pnew = par ^ 1;

        // ---- GRU: 32 warps = 8 row-groups x 4 k-slices; j = g*148 + blk ----
        {
            int g = w >> 2, sub = w & 3;
            int j = g * NBLK + blk;
            if (j < 1024) {
                int k4 = sub * 64;
                const float4* xv = (const float4*)(emb_table + (size_t)word * 1024) + k4;
                const float4* hv = (const float4*)g_h[pold] + k4;
                const float4* m0 = (const float4*)(W_ih + (size_t)j * 1024) + k4;
                const float4* m1 = (const float4*)(W_ih + (size_t)(1024 + j) * 1024) + k4;
                const float4* m2 = (const float4*)(W_ih + (size_t)(2048 + j) * 1024) + k4;
                const float4* m3 = (const float4*)(W_hh + (size_t)j * 1024) + k4;
                const float4* m4p = (const float4*)(W_hh + (size_t)(1024 + j) * 1024) + k4;
                const float4* m5 = (const float4*)(W_hh + (size_t)(2048 + j) * 1024) + k4;
                float a0 = 0, a1 = 0, a2 = 0, a3 = 0, a4 = 0, a5 = 0;
#pragma unroll
                for (int i = 0; i < 2; i++) {
                    int k = lane + 32 * i;
                    float4 x = __ldg(xv + k);
                    float4 h = __ldcg(hv + k);
                    float4 m;
                    m = __ldg(m0 + k); a0 = fmaf(m.x, x.x, a0); a0 = fmaf(m.y, x.y, a0); a0 = fmaf(m.z, x.z, a0); a0 = fmaf(m.w, x.w, a0);
                    m = __ldg(m1 + k); a1 = fmaf(m.x, x.x, a1); a1 = fmaf(m.y, x.y, a1); a1 = fmaf(m.z, x.z, a1); a1 = fmaf(m.w, x.w, a1);
                    m = __ldg(m2 + k); a2 = fmaf(m.x, x.x, a2); a2 = fmaf(m.y, x.y, a2); a2 = fmaf(m.z, x.z, a2); a2 = fmaf(m.w, x.w, a2);
                    m = __ldg(m3 + k); a3 = fmaf(m.x, h.x, a3); a3 = fmaf(m.y, h.y, a3); a3 = fmaf(m.z, h.z, a3); a3 = fmaf(m.w, h.w, a3);
                    m = __ldg(m4p + k); a4 = fmaf(m.x, h.x, a4); a4 = fmaf(m.y, h.y, a4); a4 = fmaf(m.z, h.z, a4); a4 = fmaf(m.w, h.w, a4);
                    m = __ldg(m5 + k); a5 = fmaf(m.x, h.x, a5); a5 = fmaf(m.y, h.y, a5); a5 = fmaf(m.z, h.z, a5); a5 = fmaf(m.w, h.w, a5);
                }
                a0 = warp_sum(a0); a1 = warp_sum(a1); a2 = warp_sum(a2);
                a3 = warp_sum(a3); a4 = warp_sum(a4); a5 = warp_sum(a5);
                if (lane == 0) {
                    s_gru[g][sub][0] = a0; s_gru[g][sub][1] = a1; s_gru[g][sub][2] = a2;
                    s_gru[g][sub][3] = a3; s_gru[g][sub][4] = a4; s_gru[g][sub][5] = a5;
                }
            }
            __syncthreads();
            if (tid < 8) {
                int jo = tid * NBLK + blk;
                if (jo < 1024) {
                    float D[6];
#pragma unroll
                    for (int d = 0; d < 6; d++)
                        D[d] = s_gru[tid][0][d] + s_gru[tid][1][d] + s_gru[tid][2][d] + s_gru[tid][3][d];
                    float gr = D[0] + __ldg(&b_ih[jo]);
                    float gz = D[1] + __ldg(&b_ih[1024 + jo]);
                    float gn = D[2] + __ldg(&b_ih[2048 + jo]);
                    float hr = D[3] + __ldg(&b_hh[jo]);
                    float hz = D[4] + __ldg(&b_hh[1024 + jo]);
                    float hn = D[5] + __ldg(&b_hh[2048 + jo]);
                    float r = sigmoid_fast(gr + hr);
                    float z = sigmoid_fast(gz + hz);
                    float n = tanh_fast(gn + r * hn);
                    float hold = __ldcg(&g_h[pold][jo]);
                    __stcg(&g_h[pnew][jo], (1.f - z) * n + z * hold);
                }
            }
        }
        gsync(tgt);
        if (blk == 0 && tid == 0) {
            atomicExch(&g_M[par ^ 1], 0u);
            atomicExch(&g_best[par ^ 1], 0ull);
        }

        // ---- q[a] = h_new . Wq[a,:] ----
        {
            int a = w * NBLK + blk;
            if (w < 7 && a < 1024) {
                const float4* mq = (const float4*)(Wq + (size_t)a * 1024);
                const float4* hv = (const float4*)g_h[pnew];
                float acc = 0.f;
#pragma unroll
                for (int i = 0; i < 8; i++) {
                    int k = lane + 32 * i;
                    float4 m = __ldg(mq + k);
                    float4 h = __ldcg(hv + k);
                    acc = fmaf(m.x, h.x, acc); acc = fmaf(m.y, h.y, acc);
                    acc = fmaf(m.z, h.z, acc); acc = fmaf(m.w, h.w, acc);
                }
                acc = warp_sum(acc);
                if (lane == 0) __stcg(&g_q[a], acc);
            }
        }
        gsync(tgt);

        // ---- s[j] = sum_a tanh(eproj[j,a] + q[a]) * v_a[a] ----
        {
            int j = w * NBLK + blk;
            if (w < 14 && j < 2048) {
                const float4* ep = (const float4*)(g_eproj + (size_t)j * 1024);
                const float4* qv = (const float4*)g_q;
                const float4* vv = (const float4*)va;
                float acc = 0.f;
#pragma unroll 4
                for (int i = 0; i < 8; i++) {
                    int k = lane + 32 * i;
                    float4 e4 = __ldg(ep + k);
                    float4 q4 = __ldcg(qv + k);
                    float4 v4 = __ldg(vv + k);
                    acc = fmaf(tanh_fast(e4.x + q4.x), v4.x, acc);
                    acc = fmaf(tanh_fast(e4.y + q4.y), v4.y, acc);
                    acc = fmaf(tanh_fast(e4.z + q4.z), v4.z, acc);
                    acc = fmaf(tanh_fast(e4.w + q4.w), v4.w, acc);
                }
                acc = warp_sum(acc);
                if (lane == 0) __stcg(&g_s[j], acc);
            }
        }
        gsync(tgt);

        // ---- softmax (redundant stats) + ctx partials + weights output ----
        if (blk < 128) {
            float v2[2];
            float lm = -3.4e38f;
#pragma unroll
            for (int r = 0; r < 2; r++) {
                v2[r] = __ldcg(&g_s[tid + 1024 * r]);
                lm = fmaxf(lm, v2[r]);
            }
            lm = warp_max(lm);
            if (lane == 0) s_red[w] = lm;
            __syncthreads();
            float m = s_red[0];
#pragma unroll
            for (int k = 1; k < 32; k++) m = fmaxf(m, s_red[k]);
            __syncthreads();
            float ls = expf(v2[0] - m) + expf(v2[1] - m);
            ls = warp_sum(ls);
            if (lane == 0) s_red[w] = ls;
            __syncthreads();
            float tot = s_red[0];
#pragma unroll
            for (int k = 1; k < 32; k++) tot += s_red[k];
            float inv = 1.f / tot;

            if (blk == 0) {
                size_t base = (size_t)NBOUND + (size_t)t * SDIM;
#pragma unroll
                for (int r = 0; r < 2; r++)
                    out[base + tid + 1024 * r] = expf(v2[r] - m) * inv;
            }

            // ctx partial: sc = blk>>4 (s-chunk of 256), ac = blk&15 (a-chunk of 64)
            int sc = blk >> 4;
            int ac = blk & 15;
            int a0 = ac * 64;
            int g = tid >> 6, al = tid & 63;     // 16 groups x 64 threads
            float acc = 0.f;
            int sb = sc * 256 + g * 16;
            for (int ss = 0; ss < 16; ss++) {
                int s = sb + ss;
                float wv = expf(__ldcg(&g_s[s]) - m) * inv;
                acc = fmaf(wv, __ldg(&emb[(size_t)s * 1024 + a0 + al]), acc);
            }
            float* sred = s_As;
            sred[g * 64 + al] = acc;
            __syncthreads();
            if (tid < 64) {
                float c = 0.f;
#pragma unroll
                for (int gg = 0; gg < 16; gg++) c += sred[gg * 64 + tid];
                __stcg(&g_ctx_part[sc][a0 + tid], c);
            }
        }
        gsync(tgt);

        // ---- vocab: int8 GEMV + Cauchy-Schwarz bound (bounds in smem) ----
        float* ms = s_As;
        float l2 = 0.f;
        {
            float hv = __ldcg(&g_h[pnew][tid]);
            ms[tid] = hv;
            l2 = fmaf(hv, hv, l2);
            float c = 0.f;
#pragma unroll
            for (int p = 0; p < 8; p++) c += __ldcg(&g_ctx_part[p][tid]);
            ms[1024 + tid] = c;
            l2 = fmaf(c, c, l2);
        }
        l2 = warp_sum(l2);
        if (lane == 0) s_red[w] = l2;
        __syncthreads();
        if (tid == 0) {
            float nt = 0.f;
#pragma unroll
            for (int k = 0; k < 32; k++) nt += s_red[k];
            s_nm = sqrtf(nt);
            s_cnt = 0;
        }
        __syncthreads();
        const float4* m4 = (const float4*)ms;
        const float nm = s_nm;
        float wmax = -3.4e38f;
#pragma unroll
        for (int p = 0; p < 6; p++) {
            int v0 = gw + (2 * p) * NWTOT;
            int v1 = v0 + NWTOT;
            bool ok0 = (v0 < VDIM);
            bool ok1 = (p < 5) && (v1 < VDIM);
            float a0 = 0.f, a1 = 0.f;
            if (ok0) {
                const unsigned* q0 = (const unsigned*)(g_wq + (size_t)v0 * MERGED);
                const unsigned* q1 = (const unsigned*)(g_wq + (size_t)(ok1 ? v1 : v0) * MERGED);
#pragma unroll 8
                for (int i = 0; i < 16; i++) {
                    int idx = lane + 32 * i;
                    unsigned u0 = __ldcs(q0 + idx);
                    unsigned u1 = __ldcs(q1 + idx);
                    float4 mm = m4[idx];
                    acc_q(a0, u0, mm);
                    acc_q(a1, u1, mm);
                }
                a0 = warp_sum(a0);
                a1 = warp_sum(a1);
            }
            if (lane == 0) {
                if (ok0) {
                    float A0 = a0 * __ldg(&g_scale[v0]) + __ldg(&bout[v0]);
                    float B0 = fmaf(__ldg(&g_qb[v0]), nm, 3e-3f);
                    s_ub[w][2 * p] = A0 + B0;
                    wmax = fmaxf(wmax, A0 - B0);
                } else if (2 * p < 11) s_ub[w][2 * p] = -3.4e38f;
                if (ok1) {
                    float A1 = a1 * __ldg(&g_scale[v1]) + __ldg(&bout[v1]);
                    float B1 = fmaf(__ldg(&g_qb[v1]), nm, 3e-3f);
                    s_ub[w][2 * p + 1] = A1 + B1;
                    wmax = fmaxf(wmax, A1 - B1);
                } else if (2 * p + 1 < 11) s_ub[w][2 * p + 1] = -3.4e38f;
            }
        }
        wmax = warp_max(wmax);
        if (lane == 0) s_red[w] = wmax;
        __syncthreads();
        if (tid == 0) {
            float bm = s_red[0];
#pragma unroll
            for (int k = 1; k < 32; k++) bm = fmaxf(bm, s_red[k]);
            atomicMax(&g_M[par], enc_f(bm));
        }
        gsync(tgt);

        // ---- scan own smem bounds + exact fp32 rescore ----
        {
            float thr = dec_f(__ldcg(&g_M[par]));
            if (lane == 0) {
#pragma unroll
                for (int r = 0; r < 11; r++) {
                    if (s_ub[w][r] >= thr) {
                        int p = atomicAdd(&s_cnt, 1);
                        if (p < 32) s_cand[p] = gw + r * NWTOT;
                    }
                }
            }
        }
        __syncthreads();
        int nc = min(s_cnt, 32);
        for (int c = 0; c < nc; c++) {
            int v = s_cand[c];
            float2 rr = __ldg((const float2*)(Wout + (size_t)v * MERGED) + tid);
            float2 mm = ((const float2*)ms)[tid];
            float a = fmaf(rr.x, mm.x, rr.y * mm.y);
            a = warp_sum(a);
            if (lane == 0) s_red[w] = a;
            __syncthreads();
            if (tid == 0) {
                float L = 0.f;
#pragma unroll
                for (int k = 0; k < 32; k++) L += s_red[k];
                L += __ldg(&bout[v]);
                unsigned long long pk =
                    ((unsigned long long)enc_f(L) << 32) |
                    (unsigned long long)(0xFFFFFFFFu - (unsigned)v);
                atomicMax(&g_best[par], pk);
            }
            __syncthreads();
        }
        gsync(tgt);

        if (tid == 0) {
            unsigned long long pk = __ldcg(&g_best[par]);
            int wd = (int)(0xFFFFFFFFu - (unsigned)(pk & 0xFFFFFFFFull));
            s_word = wd;
            if (blk == 0) out[t] = (float)wd;
        }
        __syncthreads();
        word = s_word;
    }
}

// ---------------- launch ----------------
extern "C" void kernel_launch(void* const* d_in, const int* in_sizes, int n_in,
                              void* d_out, int out_size) {
    const float* hidden     = (const float*)d_in[0];
    const float* embeddings = (const float*)d_in[1];
    const float* emb_table  = (const float*)d_in[2];
    const float* W_ih       = (const float*)d_in[3];
    const float* W_hh       = (const float*)d_in[4];
    const float* b_ih       = (const float*)d_in[5];
    const float* b_hh       = (const float*)d_in[6];
    const float* W_e        = (const float*)d_in[7];
    const float* W_q        = (const float*)d_in[8];
    const float* b_a        = (const float*)d_in[9];
    const float* v_a        = (const float*)d_in[10];
    const float* W_out      = (const float*)d_in[11];
    const float* b_out      = (const float*)d_in[12];
    float* out = (float*)d_out;

    k_mega<<<NBLK, NTHR>>>(hidden, embeddings, emb_table, W_ih, W_hh, b_ih, b_hh,
                           W_e, W_q, b_a, v_a, W_out, b_out, out);
}

// round 13
// speedup vs baseline: 1.0738x; 1.0738x over previous
#include <cuda_runtime.h>
#include <cuda_bf16.h>
#include <cstdint>

#define HDIM 1024
#define SDIM 2048
#define VDIM 50257
#define NBOUND 25
#define MERGED 2048
#define NBLK 296           // 148 SMs x 2 co-resident blocks
#define NTHR 512
#define NWTOT (NBLK * 16)  // 4736 warps

// ---------------- device scratch ----------------
__device__ __align__(16) float g_h[2][HDIM];
__device__ __align__(16) float g_q[HDIM];
__device__ __align__(16) float g_s[SDIM];
__device__ __align__(16) float g_ctx_part[8][HDIM];
__device__ __align__(16) float g_eproj[(size_t)SDIM * HDIM];          // 8 MB
__device__ __align__(16) unsigned char g_wq[(size_t)VDIM * MERGED];   // 103 MB int8 W_out
__device__ __align__(16) float g_scale[VDIM];                         // per-row scale s_w
__device__ __align__(16) float g_qb[VDIM];                            // per-row ||w - s_w q||
__device__ __align__(16) float g_wn[VDIM];                            // per-row s_w*||q||
__device__ unsigned g_M[2];
__device__ unsigned long long g_best[2];
__device__ unsigned g_bar_count, g_bar_phase;

// ---------------- helpers ----------------
__device__ __forceinline__ float warp_sum(float v) {
#pragma unroll
    for (int o = 16; o; o >>= 1) v += __shfl_xor_sync(0xffffffffu, v, o);
    return v;
}
__device__ __forceinline__ int warp_sum_i(int v) {
#pragma unroll
    for (int o = 16; o; o >>= 1) v += __shfl_xor_sync(0xffffffffu, v, o);
    return v;
}
__device__ __forceinline__ float warp_max(float v) {
#pragma unroll
    for (int o = 16; o; o >>= 1) v = fmaxf(v, __shfl_xor_sync(0xffffffffu, v, o));
    return v;
}
__device__ __forceinline__ unsigned enc_f(float f) {
    unsigned b = __float_as_uint(f);
    return (b & 0x80000000u) ? ~b : (b | 0x80000000u);
}
__device__ __forceinline__ float dec_f(unsigned u) {
    unsigned b = (u & 0x80000000u) ? (u ^ 0x80000000u) : ~u;
    return __uint_as_float(b);
}
__device__ __forceinline__ float exp2_fast(float y) {
    y = fminf(fmaxf(y, -60.f), 60.f);
    float n = rintf(y);
    float f = y - n;
    float p = 1.5403530e-4f;
    p = fmaf(p, f, 1.3333558e-3f);
    p = fmaf(p, f, 9.6181291e-3f);
    p = fmaf(p, f, 5.5504109e-2f);
    p = fmaf(p, f, 2.4022651e-1f);
    p = fmaf(p, f, 6.9314718e-1f);
    p = fmaf(p, f, 1.0f);
    return __int_as_float(((int)n + 127) << 23) * p;
}
__device__ __forceinline__ float tanh_fast(float x) {
    float e = exp2_fast(x * 2.885390081777927f);
    return 1.f - 2.f / (e + 1.f);
}
__device__ __forceinline__ float sigmoid_fast(float x) {
    float e = exp2_fast(-1.4426950408889634f * x);
    return 1.f / (1.f + e);
}

// grid-wide barrier
__device__ __forceinline__ void gsync(unsigned& tgt) {
    __syncthreads();
    if (threadIdx.x == 0) {
        __threadfence();
        unsigned v = atomicAdd(&g_bar_count, 1u);
        if (v == NBLK - 1) {
            g_bar_count = 0;
            asm volatile("st.release.gpu.u32 [%0], %1;" :: "l"(&g_bar_phase), "r"(tgt) : "memory");
        } else {
            unsigned p;
            do {
                asm volatile("ld.acquire.gpu.u32 %0, [%1];" : "=r"(p) : "l"(&g_bar_phase) : "memory");
            } while ((int)(p - tgt) < 0);
        }
    }
    __syncthreads();
    tgt++;
}

// ---------------- the persistent mega-kernel ----------------
__global__ __launch_bounds__(NTHR, 2) void k_mega(
    const float* __restrict__ hidden, const float* __restrict__ emb,
    const float* __restrict__ emb_table,
    const float* __restrict__ W_ih, const float* __restrict__ W_hh,
    const float* __restrict__ b_ih, const float* __restrict__ b_hh,
    const float* __restrict__ We, const float* __restrict__ Wq,
    const float* __restrict__ ba, const float* __restrict__ va,
    const float* __restrict__ Wout, const float* __restrict__ bout,
    float* __restrict__ out)
{
    __shared__ __align__(16) float s_As[128 * 36];   // eproj A tile; reused as merge vec
    __shared__ __align__(16) float s_Bs[64 * 33];    // eproj B tile
    __shared__ __align__(16) int s_hi[512];          // packed int8 hi of m (4/elem)
    __shared__ __align__(16) int s_lo[512];          // packed int8 lo of m
    __shared__ float s_gru[4][4][6];
    __shared__ float s_red[16];
    __shared__ float s_red2[16];
    __shared__ float s_ub[16][11];                   // per-warp row upper bounds
    __shared__ float s_nm, s_sm, s_inv, s_rmn;
    __shared__ int s_cand[32];
    __shared__ int s_cnt;
    __shared__ int s_word;

    const int tid = threadIdx.x;
    const int blk = blockIdx.x;
    const int w = tid >> 5, lane = tid & 31;
    const int gw = blk * 16 + w;

    unsigned tgt = *((volatile unsigned*)&g_bar_phase) + 1;

    // ---------- phase 0a: init + int8 quant of W_out (warp per row) ----------
    if (blk == 0 && tid < 2) { g_M[tid] = 0u; g_best[tid] = 0ull; }
    if (blk == 1) {
        for (int i = tid; i < HDIM; i += NTHR) g_h[0][i] = hidden[i];
    }
    for (int v = gw; v < VDIM; v += NWTOT) {
        const float4* src = (const float4*)(Wout + (size_t)v * MERGED);
        float am = 0.f;
#pragma unroll 4
        for (int i = 0; i < 16; i++) {
            float4 f = __ldg(src + lane + 32 * i);
            am = fmaxf(am, fmaxf(fmaxf(fabsf(f.x), fabsf(f.y)), fmaxf(fabsf(f.z), fabsf(f.w))));
        }
        am = warp_max(am);
        am = fmaxf(am, 1e-20f);
        float scale = am * (1.f / 127.f);
        float inv = 127.f / am;
        unsigned* dst = (unsigned*)(g_wq + (size_t)v * MERGED);
        float r2 = 0.f;
        float q2 = 0.f;
#pragma unroll 4
        for (int i = 0; i < 16; i++) {
            float4 f = __ldg(src + lane + 32 * i);
            int q0 = min(127, max(-127, __float2int_rn(f.x * inv)));
            int q1 = min(127, max(-127, __float2int_rn(f.y * inv)));
            int q2i = min(127, max(-127, __float2int_rn(f.z * inv)));
            int q3 = min(127, max(-127, __float2int_rn(f.w * inv)));
            float r0 = f.x - (float)q0 * scale;
            float r1 = f.y - (float)q1 * scale;
            float rr2 = f.z - (float)q2i * scale;
            float r3 = f.w - (float)q3 * scale;
            r2 = fmaf(r0, r0, r2); r2 = fmaf(r1, r1, r2);
            r2 = fmaf(rr2, rr2, r2); r2 = fmaf(r3, r3, r2);
            q2 += (float)(q0 * q0 + q1 * q1 + q2i * q2i + q3 * q3);
            unsigned pk = (q0 & 0xFF) | ((q1 & 0xFF) << 8) | ((q2i & 0xFF) << 16) | ((unsigned)(q3 & 0xFF) << 24);
            __stcs(dst + lane + 32 * i, pk);
        }
        r2 = warp_sum(r2);
        q2 = warp_sum(q2);
        if (lane == 0) {
            g_scale[v] = scale;
            g_qb[v] = sqrtf(r2);
            g_wn[v] = scale * sqrtf(q2);
        }
    }

    // ---------- phase 0b: eproj (blocks 0-255, one 128x64 tile each) ----------
    if (blk < 256) {
        const int ts0 = (blk >> 4) * 128;
        const int ta0 = (blk & 15) * 64;
        const int ts = tid >> 4;
        const int ta = tid & 15;
        float acc[4][4];
#pragma unroll
        for (int i = 0; i < 4; i++)
#pragma unroll
            for (int j = 0; j < 4; j++) acc[i][j] = 0.f;
        __syncthreads();
        for (int kt = 0; kt < 1024; kt += 32) {
#pragma unroll
            for (int r = 0; r < 8; r++) {
                int e0 = tid + NTHR * r;
                int si = e0 >> 5, kk = e0 & 31;
                s_As[si * 36 + kk] = emb[(size_t)(ts0 + si) * 1024 + kt + kk];
            }
#pragma unroll
            for (int r = 0; r < 4; r++) {
                int e0 = tid + NTHR * r;
                int ai = e0 >> 5, kk = e0 & 31;
                s_Bs[ai * 33 + kk] = We[(size_t)(ta0 + ai) * 1024 + kt + kk];
            }
            __syncthreads();
#pragma unroll
            for (int k = 0; k < 32; k++) {
                float a0 = s_As[ts * 36 + k];
                float a1 = s_As[(ts + 32) * 36 + k];
                float a2 = s_As[(ts + 64) * 36 + k];
                float a3 = s_As[(ts + 96) * 36 + k];
                float b0 = s_Bs[(ta * 4 + 0) * 33 + k];
                float b1 = s_Bs[(ta * 4 + 1) * 33 + k];
                float b2 = s_Bs[(ta * 4 + 2) * 33 + k];
                float b3 = s_Bs[(ta * 4 + 3) * 33 + k];
                acc[0][0] = fmaf(a0, b0, acc[0][0]); acc[0][1] = fmaf(a0, b1, acc[0][1]);
                acc[0][2] = fmaf(a0, b2, acc[0][2]); acc[0][3] = fmaf(a0, b3, acc[0][3]);
                acc[1][0] = fmaf(a1, b0, acc[1][0]); acc[1][1] = fmaf(a1, b1, acc[1][1]);
                acc[1][2] = fmaf(a1, b2, acc[1][2]); acc[1][3] = fmaf(a1, b3, acc[1][3]);
                acc[2][0] = fmaf(a2, b0, acc[2][0]); acc[2][1] = fmaf(a2, b1, acc[2][1]);
                acc[2][2] = fmaf(a2, b2, acc[2][2]); acc[2][3] = fmaf(a2, b3, acc[2][3]);
                acc[3][0] = fmaf(a3, b0, acc[3][0]); acc[3][1] = fmaf(a3, b1, acc[3][1]);
                acc[3][2] = fmaf(a3, b2, acc[3][2]); acc[3][3] = fmaf(a3, b3, acc[3][3]);
            }
            __syncthreads();
        }
        float4 bb = __ldg((const float4*)(ba + ta0) + ta);
#pragma unroll
        for (int i = 0; i < 4; i++) {
            float4 o = make_float4(acc[i][0] + bb.x, acc[i][1] + bb.y,
                                   acc[i][2] + bb.z, acc[i][3] + bb.w);
            *(float4*)&g_eproj[(size_t)(ts0 + ts + 32 * i) * 1024 + ta0 + ta * 4] = o;
        }
    }
    gsync(tgt);

    // ---------- decode loop ----------
    int word = 1;  // SOS
    for (int t = 0; t < NBOUND; t++) {
        const int par = t & 1;
        const int pold = par, pnew = par ^ 1;

        // ---- GRU: 16 warps = 4 rows/block x 4 k-slices ----
        {
            int g = w >> 2, sub = w & 3;
            int j = blk * 4 + g;
            if (j < 1024) {
                int k4 = sub * 64;
                const float4* xv = (const float4*)(emb_table + (size_t)word * 1024) + k4;
                const float4* hv = (const float4*)g_h[pold] + k4;
                const float4* m0 = (const float4*)(W_ih + (size_t)j * 1024) + k4;
                const float4* m1 = (const float4*)(W_ih + (size_t)(1024 + j) * 1024) + k4;
                const float4* m2 = (const float4*)(W_ih + (size_t)(2048 + j) * 1024) + k4;
                const float4* m3 = (const float4*)(W_hh + (size_t)j * 1024) + k4;
                const float4* m4p = (const float4*)(W_hh + (size_t)(1024 + j) * 1024) + k4;
                const float4* m5 = (const float4*)(W_hh + (size_t)(2048 + j) * 1024) + k4;
                float a0 = 0, a1 = 0, a2 = 0, a3 = 0, a4 = 0, a5 = 0;
#pragma unroll
                for (int i = 0; i < 2; i++) {
                    int k = lane + 32 * i;
                    float4 x = __ldg(xv + k);
                    float4 h = __ldcg(hv + k);
                    float4 m;
                    m = __ldg(m0 + k); a0 = fmaf(m.x, x.x, a0); a0 = fmaf(m.y, x.y, a0); a0 = fmaf(m.z, x.z, a0); a0 = fmaf(m.w, x.w, a0);
                    m = __ldg(m1 + k); a1 = fmaf(m.x, x.x, a1); a1 = fmaf(m.y, x.y, a1); a1 = fmaf(m.z, x.z, a1); a1 = fmaf(m.w, x.w, a1);
                    m = __ldg(m2 + k); a2 = fmaf(m.x, x.x, a2); a2 = fmaf(m.y, x.y, a2); a2 = fmaf(m.z, x.z, a2); a2 = fmaf(m.w, x.w, a2);
                    m = __ldg(m3 + k); a3 = fmaf(m.x, h.x, a3); a3 = fmaf(m.y, h.y, a3); a3 = fmaf(m.z, h.z, a3); a3 = fmaf(m.w, h.w, a3);
                    m = __ldg(m4p + k); a4 = fmaf(m.x, h.x, a4); a4 = fmaf(m.y, h.y, a4); a4 = fmaf(m.z, h.z, a4); a4 = fmaf(m.w, h.w, a4);
                    m = __ldg(m5 + k); a5 = fmaf(m.x, h.x, a5); a5 = fmaf(m.y, h.y, a5); a5 = fmaf(m.z, h.z, a5); a5 = fmaf(m.w, h.w, a5);
                }
                a0 = warp_sum(a0); a1 = warp_sum(a1); a2 = warp_sum(a2);
                a3 = warp_sum(a3); a4 = warp_sum(a4); a5 = warp_sum(a5);
                if (lane == 0) {
                    s_gru[g][sub][0] = a0; s_gru[g][sub][1] = a1; s_gru[g][sub][2] = a2;
                    s_gru[g][sub][3] = a3; s_gru[g][sub][4] = a4; s_gru[g][sub][5] = a5;
                }
            }
            __syncthreads();
            if (tid < 4) {
                int jo = blk * 4 + tid;
                if (jo < 1024) {
                    float D[6];
#pragma unroll
                    for (int d = 0; d < 6; d++)
                        D[d] = s_gru[tid][0][d] + s_gru[tid][1][d] + s_gru[tid][2][d] + s_gru[tid][3][d];
                    float gr = D[0] + __ldg(&b_ih[jo]);
                    float gz = D[1] + __ldg(&b_ih[1024 + jo]);
                    float gn = D[2] + __ldg(&b_ih[2048 + jo]);
                    float hr = D[3] + __ldg(&b_hh[jo]);
                    float hz = D[4] + __ldg(&b_hh[1024 + jo]);
                    float hn = D[5] + __ldg(&b_hh[2048 + jo]);
                    float r = sigmoid_fast(gr + hr);
                    float z = sigmoid_fast(gz + hz);
                    float n = tanh_fast(gn + r * hn);
                    float hold = __ldcg(&g_h[pold][jo]);
                    __stcg(&g_h[pnew][jo], (1.f - z) * n + z * hold);
                }
            }
        }
        gsync(tgt);
        if (blk == 0 && tid == 0) {
            atomicExch(&g_M[par ^ 1], 0u);
            atomicExch(&g_best[par ^ 1], 0ull);
        }

        // ---- q[a] = h_new . Wq[a,:] ----
        {
            int a = w * NBLK + blk;
            if (w < 4 && a < 1024) {
                const float4* mq = (const float4*)(Wq + (size_t)a * 1024);
                const float4* hv = (const float4*)g_h[pnew];
                float acc = 0.f;
#pragma unroll
                for (int i = 0; i < 8; i++) {
                    int k = lane + 32 * i;
                    float4 m = __ldg(mq + k);
                    float4 h = __ldcg(hv + k);
                    acc = fmaf(m.x, h.x, acc); acc = fmaf(m.y, h.y, acc);
                    acc = fmaf(m.z, h.z, acc); acc = fmaf(m.w, h.w, acc);
                }
                acc = warp_sum(acc);
                if (lane == 0) __stcg(&g_q[a], acc);
            }
        }
        gsync(tgt);

        // ---- s[j] = sum_a tanh(eproj[j,a] + q[a]) * v_a[a] ----
        {
            int j = w * NBLK + blk;
            if (w < 7 && j < 2048) {
                const float4* ep = (const float4*)(g_eproj + (size_t)j * 1024);
                const float4* qv = (const float4*)g_q;
                const float4* vv = (const float4*)va;
                float acc = 0.f;
#pragma unroll 4
                for (int i = 0; i < 8; i++) {
                    int k = lane + 32 * i;
                    float4 e4 = __ldg(ep + k);
                    float4 q4 = __ldcg(qv + k);
                    float4 v4 = __ldg(vv + k);
                    acc = fmaf(tanh_fast(e4.x + q4.x), v4.x, acc);
                    acc = fmaf(tanh_fast(e4.y + q4.y), v4.y, acc);
                    acc = fmaf(tanh_fast(e4.z + q4.z), v4.z, acc);
                    acc = fmaf(tanh_fast(e4.w + q4.w), v4.w, acc);
                }
                acc = warp_sum(acc);
                if (lane == 0) __stcg(&g_s[j], acc);
            }
        }
        gsync(tgt);

        // ---- softmax (redundant stats) + ctx partials + weights output ----
        if (blk < 128) {
            float v4[4];
            float lm = -3.4e38f;
#pragma unroll
            for (int r = 0; r < 4; r++) {
                v4[r] = __ldcg(&g_s[tid + 512 * r]);
                lm = fmaxf(lm, v4[r]);
            }
            lm = warp_max(lm);
            if (lane == 0) s_red[w] = lm;
            __syncthreads();
            float m = s_red[0];
#pragma unroll
            for (int k = 1; k < 16; k++) m = fmaxf(m, s_red[k]);
            __syncthreads();
            float ls = 0.f;
#pragma unroll
            for (int r = 0; r < 4; r++) ls += expf(v4[r] - m);
            ls = warp_sum(ls);
            if (lane == 0) s_red[w] = ls;
            __syncthreads();
            float tot = s_red[0];
#pragma unroll
            for (int k = 1; k < 16; k++) tot += s_red[k];
            float inv = 1.f / tot;

            if (blk == 0) {
                size_t base = (size_t)NBOUND + (size_t)t * SDIM;
#pragma unroll
                for (int r = 0; r < 4; r++)
                    out[base + tid + 512 * r] = expf(v4[r] - m) * inv;
            }

            int sc = blk >> 4;
            int ac = blk & 15;
            int a0 = ac * 64;
            int g = tid >> 6, al = tid & 63;
            float acc = 0.f;
            int sb = sc * 256 + g * 32;
            for (int ss = 0; ss < 32; ss++) {
                int s = sb + ss;
                float wv = expf(__ldcg(&g_s[s]) - m) * inv;
                acc = fmaf(wv, __ldg(&emb[(size_t)s * 1024 + a0 + al]), acc);
            }
            float* sred = s_As;
            sred[g * 64 + al] = acc;
            __syncthreads();
            if (tid < 64) {
                float c = 0.f;
#pragma unroll
                for (int gg = 0; gg < 8; gg++) c += sred[gg * 64 + tid];
                __stcg(&g_ctx_part[sc][a0 + tid], c);
            }
        }
        gsync(tgt);

        // ---- build merge (FULL 2048), quantize m exactly to int16 (hi/lo int8), norms ----
        float* ms = s_As;
        float l2 = 0.f;
        for (int i = tid; i < 1024; i += NTHR) {
            float hv = __ldcg(&g_h[pnew][i]);
            ms[i] = hv;
            l2 = fmaf(hv, hv, l2);
        }
        for (int i = tid; i < 1024; i += NTHR) {
            float c = 0.f;
#pragma unroll
            for (int p = 0; p < 8; p++) c += __ldcg(&g_ctx_part[p][i]);
            ms[1024 + i] = c;
            l2 = fmaf(c, c, l2);
        }
        l2 = warp_sum(l2);
        if (lane == 0) s_red[w] = l2;
        __syncthreads();
        if (tid == 0) {
            float nt = 0.f;
#pragma unroll
            for (int k = 0; k < 16; k++) nt += s_red[k];
            s_nm = sqrtf(nt);
            s_cnt = 0;
        }
        // absmax of m
        float4 mf = ((const float4*)ms)[tid];
        float am4 = fmaxf(fmaxf(fabsf(mf.x), fabsf(mf.y)), fmaxf(fabsf(mf.z), fabsf(mf.w)));
        am4 = warp_max(am4);
        if (lane == 0) s_red2[w] = am4;
        __syncthreads();
        if (tid == 0) {
            float am = s_red2[0];
#pragma unroll
            for (int k = 1; k < 16; k++) am = fmaxf(am, s_red2[k]);
            am = fmaxf(am, 1e-20f);
            s_sm = am * (1.f / 32512.f);
            s_inv = 32512.f / am;
        }
        __syncthreads();
        // pack hi/lo, residual norm
        {
            float smv = s_sm, siv = s_inv;
            int mi0 = __float2int_rn(mf.x * siv);
            int mi1 = __float2int_rn(mf.y * siv);
            int mi2 = __float2int_rn(mf.z * siv);
            int mi3 = __float2int_rn(mf.w * siv);
            int h0 = (mi0 + 128) >> 8, h1 = (mi1 + 128) >> 8, h2 = (mi2 + 128) >> 8, h3 = (mi3 + 128) >> 8;
            int l0 = mi0 - (h0 << 8), l1 = mi1 - (h1 << 8), l2i = mi2 - (h2 << 8), l3 = mi3 - (h3 << 8);
            s_hi[tid] = (h0 & 0xFF) | ((h1 & 0xFF) << 8) | ((h2 & 0xFF) << 16) | ((unsigned)(h3 & 0xFF) << 24);
            s_lo[tid] = (l0 & 0xFF) | ((l1 & 0xFF) << 8) | ((l2i & 0xFF) << 16) | ((unsigned)(l3 & 0xFF) << 24);
            float r0 = mf.x - (float)mi0 * smv;
            float r1 = mf.y - (float)mi1 * smv;
            float r2 = mf.z - (float)mi2 * smv;
            float r3 = mf.w - (float)mi3 * smv;
            float rr = fmaf(r0, r0, fmaf(r1, r1, fmaf(r2, r2, r3 * r3)));
            rr = warp_sum(rr);
            if (lane == 0) s_red[w] = rr;
        }
        __syncthreads();
        if (tid == 0) {
            float rt = 0.f;
#pragma unroll
            for (int k = 0; k < 16; k++) rt += s_red[k];
            s_rmn = sqrtf(rt);
        }
        __syncthreads();

        // ---- vocab: dp4a int8 GEMV + rigorous bound ----
        const float nm = s_nm;
        const float rmn = s_rmn;
        const float smv = s_sm;
        float wmax = -3.4e38f;
#pragma unroll
        for (int p = 0; p < 6; p++) {
            int v0 = gw + (2 * p) * NWTOT;
            int v1 = v0 + NWTOT;
            bool ok0 = (v0 < VDIM);
            bool ok1 = (p < 5) && (v1 < VDIM);
            int ah0 = 0, al0 = 0, ah1 = 0, al1 = 0;
            if (ok0) {
                const int* q0 = (const int*)(g_wq + (size_t)v0 * MERGED);
                const int* q1 = (const int*)(g_wq + (size_t)(ok1 ? v1 : v0) * MERGED);
#pragma unroll 8
                for (int i = 0; i < 16; i++) {
                    int idx = lane + 32 * i;
                    int u0 = __ldcs(q0 + idx);
                    int u1 = __ldcs(q1 + idx);
                    int ph = s_hi[idx];
                    int pl = s_lo[idx];
                    ah0 = __dp4a(u0, ph, ah0);
                    al0 = __dp4a(u0, pl, al0);
                    ah1 = __dp4a(u1, ph, ah1);
                    al1 = __dp4a(u1, pl, al1);
                }
                ah0 = warp_sum_i(ah0); al0 = warp_sum_i(al0);
                ah1 = warp_sum_i(ah1); al1 = warp_sum_i(al1);
            }
            if (lane == 0) {
                if (ok0) {
                    long long ll = 256ll * (long long)ah0 + (long long)al0;
                    float A0 = (float)ll * (__ldg(&g_scale[v0]) * smv) + __ldg(&bout[v0]);
                    float B0 = fmaf(__ldg(&g_qb[v0]), nm, fmaf(__ldg(&g_wn[v0]), rmn, 2e-3f));
                    s_ub[w][2 * p] = A0 + B0;
                    wmax = fmaxf(wmax, A0 - B0);
                } else if (2 * p < 11) s_ub[w][2 * p] = -3.4e38f;
                if (ok1) {
                    long long ll = 256ll * (long long)ah1 + (long long)al1;
                    float A1 = (float)ll * (__ldg(&g_scale[v1]) * smv) + __ldg(&bout[v1]);
                    float B1 = fmaf(__ldg(&g_qb[v1]), nm, fmaf(__ldg(&g_wn[v1]), rmn, 2e-3f));
                    s_ub[w][2 * p + 1] = A1 + B1;
                    wmax = fmaxf(wmax, A1 - B1);
                } else if (2 * p + 1 < 11) s_ub[w][2 * p + 1] = -3.4e38f;
            }
        }
        wmax = warp_max(wmax);
        if (lane == 0) s_red[w] = wmax;
        __syncthreads();
        if (tid == 0) {
            float bm = s_red[0];
#pragma unroll
            for (int k = 1; k < 16; k++) bm = fmaxf(bm, s_red[k]);
            atomicMax(&g_M[par], enc_f(bm));
        }
        gsync(tgt);

        // ---- scan own smem bounds + exact fp32 rescore ----
        {
            float thr = dec_f(__ldcg(&g_M[par]));
            if (lane == 0) {
#pragma unroll
                for (int r = 0; r < 11; r++) {
                    if (s_ub[w][r] >= thr) {
                        int p = atomicAdd(&s_cnt, 1);
                        if (p < 32) s_cand[p] = gw + r * NWTOT;
                    }
                }
            }
        }
        __syncthreads();
        int nc = min(s_cnt, 32);
        for (int c = 0; c < nc; c++) {
            int v = s_cand[c];
            float4 rr = __ldg((const float4*)(Wout + (size_t)v * MERGED) + tid);
            float4 mm = ((const float4*)ms)[tid];
            float a = fmaf(rr.x, mm.x, fmaf(rr.y, mm.y, fmaf(rr.z, mm.z, rr.w * mm.w)));
            a = warp_sum(a);
            if (lane == 0) s_red[w] = a;
            __syncthreads();
            if (tid == 0) {
                float L = 0.f;
#pragma unroll
                for (int k = 0; k < 16; k++) L += s_red[k];
                L += __ldg(&bout[v]);
                unsigned long long pk =
                    ((unsigned long long)enc_f(L) << 32) |
                    (unsigned long long)(0xFFFFFFFFu - (unsigned)v);
                atomicMax(&g_best[par], pk);
            }
            __syncthreads();
        }
        gsync(tgt);

        if (tid == 0) {
            unsigned long long pk = __ldcg(&g_best[par]);
            int wd = (int)(0xFFFFFFFFu - (unsigned)(pk & 0xFFFFFFFFull));
            s_word = wd;
            if (blk == 0) out[t] = (float)wd;
        }
        __syncthreads();
        word = s_word;
    }
}

// ---------------- launch ----------------
extern "C" void kernel_launch(void* const* d_in, const int* in_sizes, int n_in,
                              void* d_out, int out_size) {
    const float* hidden     = (const float*)d_in[0];
    const float* embeddings = (const float*)d_in[1];
    const float* emb_table  = (const float*)d_in[2];
    const float* W_ih       = (const float*)d_in[3];
    const float* W_hh       = (const float*)d_in[4];
    const float* b_ih       = (const float*)d_in[5];
    const float* b_hh       = (const float*)d_in[6];
    const float* W_e        = (const float*)d_in[7];
    const float* W_q        = (const float*)d_in[8];
    const float* b_a        = (const float*)d_in[9];
    const float* v_a        = (const float*)d_in[10];
    const float* W_out      = (const float*)d_in[11];
    const float* b_out      = (const float*)d_in[12];
    float* out = (float*)d_out;

    k_mega<<<NBLK, NTHR>>>(hidden, embeddings, emb_table, W_ih, W_hh, b_ih, b_hh,
                           W_e, W_q, b_a, v_a, W_out, b_out, out);
}